// round 1
// baseline (speedup 1.0000x reference)
#include <cuda_runtime.h>

#define C_CH   128
#define NGROUP 32
#define CPG    4
#define BMAX   64
#define EPSF   1e-5f

// Scratch (no allocations allowed): segment accumulators + folded affine tables.
__device__ double g_sum[BMAX * C_CH];
__device__ double g_sqs[BMAX * C_CH];
__device__ float4 g_scale[BMAX * NGROUP];
__device__ float4 g_shift[BMAX * NGROUP];

// ---------------------------------------------------------------------------
// 0) zero the accumulators (runs every graph replay)
// ---------------------------------------------------------------------------
__global__ void dogn_init() {
    int i = blockIdx.x * blockDim.x + threadIdx.x;
    if (i < BMAX * C_CH) {
        g_sum[i] = 0.0;
        g_sqs[i] = 0.0;
    }
}

// ---------------------------------------------------------------------------
// 1) segment sums of x and x^2 per (batch, channel).
//    Thread owns float4 lane = one group (4 consecutive channels).
//    blockDim = 256 -> 8 rows per iteration per block.
// ---------------------------------------------------------------------------
__device__ __forceinline__ void flush_stats(int b, int lane,
                                            float s0, float s1, float s2, float s3,
                                            float q0, float q1, float q2, float q3) {
    double* ps = &g_sum[b * C_CH + lane * 4];
    double* pq = &g_sqs[b * C_CH + lane * 4];
    atomicAdd(ps + 0, (double)s0);
    atomicAdd(ps + 1, (double)s1);
    atomicAdd(ps + 2, (double)s2);
    atomicAdd(ps + 3, (double)s3);
    atomicAdd(pq + 0, (double)q0);
    atomicAdd(pq + 1, (double)q1);
    atomicAdd(pq + 2, (double)q2);
    atomicAdd(pq + 3, (double)q3);
}

__global__ void dogn_stats(const float4* __restrict__ data,
                           const int* __restrict__ bid,
                           int n, int rows_per_block) {
    const int lane = threadIdx.x & 31;   // float4 lane 0..31 (== group id)
    const int rsub = threadIdx.x >> 5;   // 0..7 row sub-slot
    int r0 = blockIdx.x * rows_per_block;
    int r1 = r0 + rows_per_block;
    if (r1 > n) r1 = n;

    float s0 = 0.f, s1 = 0.f, s2 = 0.f, s3 = 0.f;
    float q0 = 0.f, q1 = 0.f, q2 = 0.f, q3 = 0.f;
    int cur = -1;

    for (int r = r0 + rsub; r < r1; r += 8) {
        int b = __ldg(&bid[r]);
        if (b != cur) {
            if (cur >= 0) {
                flush_stats(cur, lane, s0, s1, s2, s3, q0, q1, q2, q3);
                s0 = s1 = s2 = s3 = 0.f;
                q0 = q1 = q2 = q3 = 0.f;
            }
            cur = b;
        }
        float4 v = __ldg(&data[(long)r * 32 + lane]);
        s0 += v.x; q0 = fmaf(v.x, v.x, q0);
        s1 += v.y; q1 = fmaf(v.y, v.y, q1);
        s2 += v.z; q2 = fmaf(v.z, v.z, q2);
        s3 += v.w; q3 = fmaf(v.w, v.w, q3);
    }
    if (cur >= 0)
        flush_stats(cur, lane, s0, s1, s2, s3, q0, q1, q2, q3);
}

// ---------------------------------------------------------------------------
// 2) finalize: one block per batch, 32 threads = 32 groups.
//    Counts via binary search on the sorted batch_id.
// ---------------------------------------------------------------------------
__device__ __forceinline__ int lower_bound_ge(const int* __restrict__ bid, int n, int key) {
    // first index i with bid[i] >= key
    int lo = 0, hi = n;
    while (lo < hi) {
        int mid = (lo + hi) >> 1;
        if (__ldg(&bid[mid]) < key) lo = mid + 1;
        else hi = mid;
    }
    return lo;
}

__global__ void dogn_finalize(const int* __restrict__ bid,
                              const float* __restrict__ w,
                              const float* __restrict__ bias,
                              const int* __restrict__ bsz_ptr,
                              int n) {
    int b = blockIdx.x;
    int B = __ldg(bsz_ptr);
    if (b >= B) return;

    __shared__ int bounds[2];
    if (threadIdx.x < 2)
        bounds[threadIdx.x] = lower_bound_ge(bid, n, b + threadIdx.x);
    __syncthreads();

    int g = threadIdx.x;
    if (g >= NGROUP) return;

    int nb = bounds[1] - bounds[0];
    double ic = 1.0 / (4.0 * (double)nb + (double)EPSF);

    double T1 = 0.0, T2 = 0.0;
#pragma unroll
    for (int k = 0; k < 4; k++) {
        T1 += g_sum[b * C_CH + g * 4 + k];
        T2 += g_sqs[b * C_CH + g * 4 + k];
    }
    double m   = T1 * ic;
    double var = (T2 - 2.0 * m * T1 + 4.0 * (double)nb * m * m) * ic;
    double is  = 1.0 / sqrt(var + (double)EPSF);

    float4 sc, sh;
    float wv, bv;
    wv = __ldg(&w[g * 4 + 0]); bv = __ldg(&bias[g * 4 + 0]);
    sc.x = (float)(is * wv);   sh.x = (float)(bv - m * is * wv);
    wv = __ldg(&w[g * 4 + 1]); bv = __ldg(&bias[g * 4 + 1]);
    sc.y = (float)(is * wv);   sh.y = (float)(bv - m * is * wv);
    wv = __ldg(&w[g * 4 + 2]); bv = __ldg(&bias[g * 4 + 2]);
    sc.z = (float)(is * wv);   sh.z = (float)(bv - m * is * wv);
    wv = __ldg(&w[g * 4 + 3]); bv = __ldg(&bias[g * 4 + 3]);
    sc.w = (float)(is * wv);   sh.w = (float)(bv - m * is * wv);

    g_scale[b * NGROUP + g] = sc;
    g_shift[b * NGROUP + g] = sh;
}

// ---------------------------------------------------------------------------
// 3) normalize: out = x*scale + shift, one float4 per thread.
//    A warp covers exactly one row, so the batch_id load is one broadcast.
// ---------------------------------------------------------------------------
__global__ void dogn_norm(const float4* __restrict__ data,
                          const int* __restrict__ bid,
                          float4* __restrict__ out,
                          int n) {
    int i = blockIdx.x * blockDim.x + threadIdx.x;   // float4 index, < n*32 (< 2^31)
    int total = n * 32;
    if (i >= total) return;

    int r    = i >> 5;
    int lane = i & 31;
    int b = __ldg(&bid[r]);

    float4 sc = g_scale[b * NGROUP + lane];
    float4 sh = g_shift[b * NGROUP + lane];
    float4 v  = __ldg(&data[i]);

    v.x = fmaf(v.x, sc.x, sh.x);
    v.y = fmaf(v.y, sc.y, sh.y);
    v.z = fmaf(v.z, sc.z, sh.z);
    v.w = fmaf(v.w, sc.w, sh.w);
    out[i] = v;
}

// ---------------------------------------------------------------------------
extern "C" void kernel_launch(void* const* d_in, const int* in_sizes, int n_in,
                              void* d_out, int out_size) {
    const float* data = (const float*)d_in[0];
    const float* w    = (const float*)d_in[1];
    const float* bias = (const float*)d_in[2];
    const int*   bid  = (const int*)d_in[3];
    const int*   bsz  = (const int*)d_in[4];

    int n = in_sizes[0] / C_CH;   // number of rows

    // 0) zero accumulators
    dogn_init<<<(BMAX * C_CH + 511) / 512, 512>>>();

    // 1) stats
    const int STATS_GRID = 592;   // 4 blocks/SM on 148 SMs
    int rpb = (n + STATS_GRID - 1) / STATS_GRID;
    dogn_stats<<<STATS_GRID, 256>>>((const float4*)data, bid, n, rpb);

    // 2) finalize (one block per possible batch; kernel self-limits to B)
    dogn_finalize<<<BMAX, 64>>>(bid, w, bias, bsz, n);

    // 3) normalize
    int total = n * 32;
    int blocks = (total + 255) / 256;
    dogn_norm<<<blocks, 256>>>((const float4*)data, bid, (float4*)d_out, n);
}

// round 2
// speedup vs baseline: 1.2268x; 1.2268x over previous
#include <cuda_runtime.h>

#define C_CH   128
#define NGROUP 32
#define CPG    4
#define BMAX   64
#define BSM    16          // batches cached in smem for norm (B==16 in this problem)
#define EPSF   1e-5f

// Scratch (no allocations allowed)
__device__ double g_sum[BMAX * C_CH];
__device__ double g_sqs[BMAX * C_CH];
__device__ int    g_cnt[BMAX];
__device__ float4 g_scale[BMAX * NGROUP];
__device__ float4 g_shift[BMAX * NGROUP];

// ---------------------------------------------------------------------------
// 0) zero accumulators (every graph replay)
// ---------------------------------------------------------------------------
__global__ void dogn_init() {
    int i = blockIdx.x * blockDim.x + threadIdx.x;
    if (i < BMAX * C_CH) {
        g_sum[i] = 0.0;
        g_sqs[i] = 0.0;
    }
    if (i < BMAX) g_cnt[i] = 0;
}

// ---------------------------------------------------------------------------
// 1) segment sums of x and x^2 per (batch, channel), + row counts.
//    Thread = one float4 lane (a 4-channel group) of every 8th row.
//    4-way row unroll: all loads issued before any batch-id branch.
// ---------------------------------------------------------------------------
__device__ __forceinline__ void flush_stats(int b, int lane, int cnt,
                                            const float* s, const float* q) {
    double* ps = &g_sum[b * C_CH + lane * 4];
    double* pq = &g_sqs[b * C_CH + lane * 4];
#pragma unroll
    for (int k = 0; k < 4; k++) {
        atomicAdd(ps + k, (double)s[k]);
        atomicAdd(pq + k, (double)q[k]);
    }
    if (lane == 0) atomicAdd(&g_cnt[b], cnt);
}

__global__ void dogn_stats(const float4* __restrict__ data,
                           const int* __restrict__ bid,
                           int n, int rows_per_block) {
    const int lane = threadIdx.x & 31;   // group id 0..31
    const int rsub = threadIdx.x >> 5;   // 0..7 row sub-slot
    int r0 = blockIdx.x * rows_per_block;
    int r1 = r0 + rows_per_block;
    if (r1 > n) r1 = n;

    float s[4] = {0.f, 0.f, 0.f, 0.f};
    float q[4] = {0.f, 0.f, 0.f, 0.f};
    int cur = -1, cnt = 0;

    int r = r0 + rsub;

    // main: 4 rows per iteration, all loads front-batched (MLP ~8)
    for (; r + 24 < r1; r += 32) {
        int b0 = __ldg(&bid[r]);
        int b1 = __ldg(&bid[r + 8]);
        int b2 = __ldg(&bid[r + 16]);
        int b3 = __ldg(&bid[r + 24]);
        float4 v0 = __ldcs(&data[r * 32 + lane]);
        float4 v1 = __ldcs(&data[(r + 8) * 32 + lane]);
        float4 v2 = __ldcs(&data[(r + 16) * 32 + lane]);
        float4 v3 = __ldcs(&data[(r + 24) * 32 + lane]);

        if ((((b0 ^ cur) | (b1 ^ cur)) | ((b2 ^ cur) | (b3 ^ cur))) == 0) {
            s[0] += v0.x; q[0] = fmaf(v0.x, v0.x, q[0]);
            s[1] += v0.y; q[1] = fmaf(v0.y, v0.y, q[1]);
            s[2] += v0.z; q[2] = fmaf(v0.z, v0.z, q[2]);
            s[3] += v0.w; q[3] = fmaf(v0.w, v0.w, q[3]);
            s[0] += v1.x; q[0] = fmaf(v1.x, v1.x, q[0]);
            s[1] += v1.y; q[1] = fmaf(v1.y, v1.y, q[1]);
            s[2] += v1.z; q[2] = fmaf(v1.z, v1.z, q[2]);
            s[3] += v1.w; q[3] = fmaf(v1.w, v1.w, q[3]);
            s[0] += v2.x; q[0] = fmaf(v2.x, v2.x, q[0]);
            s[1] += v2.y; q[1] = fmaf(v2.y, v2.y, q[1]);
            s[2] += v2.z; q[2] = fmaf(v2.z, v2.z, q[2]);
            s[3] += v2.w; q[3] = fmaf(v2.w, v2.w, q[3]);
            s[0] += v3.x; q[0] = fmaf(v3.x, v3.x, q[0]);
            s[1] += v3.y; q[1] = fmaf(v3.y, v3.y, q[1]);
            s[2] += v3.z; q[2] = fmaf(v3.z, v3.z, q[2]);
            s[3] += v3.w; q[3] = fmaf(v3.w, v3.w, q[3]);
            cnt += 4;
        } else {
            int    bb[4] = {b0, b1, b2, b3};
            float4 vv[4] = {v0, v1, v2, v3};
#pragma unroll
            for (int k = 0; k < 4; k++) {
                if (bb[k] != cur) {
                    if (cnt > 0) flush_stats(cur, lane, cnt, s, q);
                    s[0] = s[1] = s[2] = s[3] = 0.f;
                    q[0] = q[1] = q[2] = q[3] = 0.f;
                    cnt = 0;
                    cur = bb[k];
                }
                s[0] += vv[k].x; q[0] = fmaf(vv[k].x, vv[k].x, q[0]);
                s[1] += vv[k].y; q[1] = fmaf(vv[k].y, vv[k].y, q[1]);
                s[2] += vv[k].z; q[2] = fmaf(vv[k].z, vv[k].z, q[2]);
                s[3] += vv[k].w; q[3] = fmaf(vv[k].w, vv[k].w, q[3]);
                cnt++;
            }
        }
    }

    // tail: single rows
    for (; r < r1; r += 8) {
        int b = __ldg(&bid[r]);
        float4 v = __ldcs(&data[r * 32 + lane]);
        if (b != cur) {
            if (cnt > 0) flush_stats(cur, lane, cnt, s, q);
            s[0] = s[1] = s[2] = s[3] = 0.f;
            q[0] = q[1] = q[2] = q[3] = 0.f;
            cnt = 0;
            cur = b;
        }
        s[0] += v.x; q[0] = fmaf(v.x, v.x, q[0]);
        s[1] += v.y; q[1] = fmaf(v.y, v.y, q[1]);
        s[2] += v.z; q[2] = fmaf(v.z, v.z, q[2]);
        s[3] += v.w; q[3] = fmaf(v.w, v.w, q[3]);
        cnt++;
    }
    if (cnt > 0) flush_stats(cur, lane, cnt, s, q);
}

// ---------------------------------------------------------------------------
// 2) finalize: one block per batch, 32 threads = 32 groups.
//    Counts come from g_cnt (filled by stats) — no binary search.
// ---------------------------------------------------------------------------
__global__ void dogn_finalize(const float* __restrict__ w,
                              const float* __restrict__ bias,
                              const int* __restrict__ bsz_ptr) {
    int b = blockIdx.x;
    int B = __ldg(bsz_ptr);
    if (b >= B) return;

    int g = threadIdx.x;
    if (g >= NGROUP) return;

    int nb = g_cnt[b];
    double ic = 1.0 / (4.0 * (double)nb + (double)EPSF);

    double T1 = 0.0, T2 = 0.0;
#pragma unroll
    for (int k = 0; k < 4; k++) {
        T1 += g_sum[b * C_CH + g * 4 + k];
        T2 += g_sqs[b * C_CH + g * 4 + k];
    }
    double m   = T1 * ic;
    double var = (T2 - 2.0 * m * T1 + 4.0 * (double)nb * m * m) * ic;
    double is  = 1.0 / sqrt(var + (double)EPSF);

    float4 sc, sh;
    float wv, bv;
    wv = __ldg(&w[g * 4 + 0]); bv = __ldg(&bias[g * 4 + 0]);
    sc.x = (float)(is * wv);   sh.x = (float)(bv - m * is * wv);
    wv = __ldg(&w[g * 4 + 1]); bv = __ldg(&bias[g * 4 + 1]);
    sc.y = (float)(is * wv);   sh.y = (float)(bv - m * is * wv);
    wv = __ldg(&w[g * 4 + 2]); bv = __ldg(&bias[g * 4 + 2]);
    sc.z = (float)(is * wv);   sh.z = (float)(bv - m * is * wv);
    wv = __ldg(&w[g * 4 + 3]); bv = __ldg(&bias[g * 4 + 3]);
    sc.w = (float)(is * wv);   sh.w = (float)(bv - m * is * wv);

    g_scale[b * NGROUP + g] = sc;
    g_shift[b * NGROUP + g] = sh;
}

// ---------------------------------------------------------------------------
// 3) normalize: out = x*scale + shift.
//    Grid-stride, 4 independent elements per loop body (loads front-batched).
//    scale/shift tables cached in shared memory (29cyc vs ~250cyc L2).
// ---------------------------------------------------------------------------
__global__ void dogn_norm(const float4* __restrict__ data,
                          const int* __restrict__ bid,
                          float4* __restrict__ out,
                          int total, const int* __restrict__ bsz_ptr) {
    __shared__ float4 s_sc[BSM * NGROUP];
    __shared__ float4 s_sh[BSM * NGROUP];

    int B = __ldg(bsz_ptr);
    bool use_smem = (B <= BSM);
    int m = (B < BSM ? B : BSM) * NGROUP;
    for (int j = threadIdx.x; j < m; j += blockDim.x) {
        s_sc[j] = g_scale[j];
        s_sh[j] = g_shift[j];
    }
    __syncthreads();

    const int stride = gridDim.x * blockDim.x;

    for (int base = blockIdx.x * blockDim.x + threadIdx.x; base < total;
         base += 4 * stride) {
        int i0 = base;
        int i1 = base + stride;
        int i2 = base + 2 * stride;
        int i3 = base + 3 * stride;
        bool p1 = i1 < total, p2 = i2 < total, p3 = i3 < total;

        // front-batch all independent loads
        int b0 = __ldg(&bid[i0 >> 5]);
        int b1 = p1 ? __ldg(&bid[i1 >> 5]) : 0;
        int b2 = p2 ? __ldg(&bid[i2 >> 5]) : 0;
        int b3 = p3 ? __ldg(&bid[i3 >> 5]) : 0;
        float4 v0 = __ldcs(&data[i0]);
        float4 v1, v2, v3;
        if (p1) v1 = __ldcs(&data[i1]);
        if (p2) v2 = __ldcs(&data[i2]);
        if (p3) v3 = __ldcs(&data[i3]);

        int l0 = i0 & 31, l1 = i1 & 31, l2 = i2 & 31, l3 = i3 & 31;

        float4 sc0, sh0, sc1, sh1, sc2, sh2, sc3, sh3;
        if (use_smem) {
            sc0 = s_sc[b0 * NGROUP + l0]; sh0 = s_sh[b0 * NGROUP + l0];
            sc1 = s_sc[b1 * NGROUP + l1]; sh1 = s_sh[b1 * NGROUP + l1];
            sc2 = s_sc[b2 * NGROUP + l2]; sh2 = s_sh[b2 * NGROUP + l2];
            sc3 = s_sc[b3 * NGROUP + l3]; sh3 = s_sh[b3 * NGROUP + l3];
        } else {
            sc0 = g_scale[b0 * NGROUP + l0]; sh0 = g_shift[b0 * NGROUP + l0];
            sc1 = g_scale[b1 * NGROUP + l1]; sh1 = g_shift[b1 * NGROUP + l1];
            sc2 = g_scale[b2 * NGROUP + l2]; sh2 = g_shift[b2 * NGROUP + l2];
            sc3 = g_scale[b3 * NGROUP + l3]; sh3 = g_shift[b3 * NGROUP + l3];
        }

        v0.x = fmaf(v0.x, sc0.x, sh0.x);
        v0.y = fmaf(v0.y, sc0.y, sh0.y);
        v0.z = fmaf(v0.z, sc0.z, sh0.z);
        v0.w = fmaf(v0.w, sc0.w, sh0.w);
        __stcs(&out[i0], v0);
        if (p1) {
            v1.x = fmaf(v1.x, sc1.x, sh1.x);
            v1.y = fmaf(v1.y, sc1.y, sh1.y);
            v1.z = fmaf(v1.z, sc1.z, sh1.z);
            v1.w = fmaf(v1.w, sc1.w, sh1.w);
            __stcs(&out[i1], v1);
        }
        if (p2) {
            v2.x = fmaf(v2.x, sc2.x, sh2.x);
            v2.y = fmaf(v2.y, sc2.y, sh2.y);
            v2.z = fmaf(v2.z, sc2.z, sh2.z);
            v2.w = fmaf(v2.w, sc2.w, sh2.w);
            __stcs(&out[i2], v2);
        }
        if (p3) {
            v3.x = fmaf(v3.x, sc3.x, sh3.x);
            v3.y = fmaf(v3.y, sc3.y, sh3.y);
            v3.z = fmaf(v3.z, sc3.z, sh3.z);
            v3.w = fmaf(v3.w, sc3.w, sh3.w);
            __stcs(&out[i3], v3);
        }
    }
}

// ---------------------------------------------------------------------------
extern "C" void kernel_launch(void* const* d_in, const int* in_sizes, int n_in,
                              void* d_out, int out_size) {
    const float* data = (const float*)d_in[0];
    const float* w    = (const float*)d_in[1];
    const float* bias = (const float*)d_in[2];
    const int*   bid  = (const int*)d_in[3];
    const int*   bsz  = (const int*)d_in[4];

    int n = in_sizes[0] / C_CH;   // rows

    // 0) zero accumulators
    dogn_init<<<(BMAX * C_CH + 511) / 512, 512>>>();

    // 1) stats
    const int STATS_GRID = 1184;   // 8 blocks/SM target on 148 SMs
    int rpb = (n + STATS_GRID - 1) / STATS_GRID;
    dogn_stats<<<STATS_GRID, 256>>>((const float4*)data, bid, n, rpb);

    // 2) finalize
    dogn_finalize<<<BMAX, 32>>>(w, bias, bsz);

    // 3) normalize (grid-stride, 4-way ILP)
    int total = n * 32;
    dogn_norm<<<1184, 256>>>((const float4*)data, bid, (float4*)d_out, total, bsz);
}

// round 3
// speedup vs baseline: 1.2638x; 1.0302x over previous
#include <cuda_runtime.h>

#define C_CH   128
#define NGROUP 32
#define CPG    4
#define BMAX   64
#define EPSF   1e-5f

// Scratch (no allocations allowed)
__device__ double g_sum[BMAX * C_CH];
__device__ double g_sqs[BMAX * C_CH];
__device__ int    g_bounds[BMAX + 1];
__device__ int    g_nseg;
__device__ float4 g_scale[BMAX * NGROUP];
__device__ float4 g_shift[BMAX * NGROUP];

// ---------------------------------------------------------------------------
// 0) setup: zero accumulators + compute segment bounds by binary search.
//    Blocks 0..15 zero the 8192 accum slots; block 16 does the searches.
// ---------------------------------------------------------------------------
__global__ void dogn_setup(const int* __restrict__ bid, int n,
                           const int* __restrict__ bsz_ptr) {
    if (blockIdx.x < 16) {
        int i = blockIdx.x * 512 + threadIdx.x;
        if (i < BMAX * C_CH) {
            g_sum[i] = 0.0;
            g_sqs[i] = 0.0;
        }
    } else {
        int B = __ldg(bsz_ptr);
        if (B > BMAX) B = BMAX;
        int t = threadIdx.x;
        if (t == 0) g_nseg = B;
        if (t <= B) {
            // first index with bid[idx] >= t
            int lo = 0, hi = n;
            while (lo < hi) {
                int mid = (lo + hi) >> 1;
                if (__ldg(&bid[mid]) < t) lo = mid + 1;
                else hi = mid;
            }
            g_bounds[t] = lo;
        }
    }
}

// ---------------------------------------------------------------------------
// 1) stats: block owns contiguous row chunk; per overlapping segment, a pure
//    load->FMA stream (no bid loads, no branches in the hot loop), then one
//    atomic flush. Thread = float4 lane (one 4-channel group), warp strides 8 rows.
// ---------------------------------------------------------------------------
__global__ void dogn_stats(const float4* __restrict__ data,
                           int n, int rows_per_block) {
    __shared__ int sb[BMAX + 1];
    __shared__ int sB;
    if (threadIdx.x == 0) sB = g_nseg;
    __syncthreads();
    int B = sB;
    for (int j = threadIdx.x; j <= B; j += blockDim.x) sb[j] = g_bounds[j];
    __syncthreads();

    const int lane = threadIdx.x & 31;
    const int rsub = threadIdx.x >> 5;
    int r0 = blockIdx.x * rows_per_block;
    int r1 = r0 + rows_per_block;
    if (r1 > n) r1 = n;
    if (r0 >= r1) return;

    for (int seg = 0; seg < B; seg++) {
        int a = sb[seg], e = sb[seg + 1];
        if (a < r0) a = r0;
        if (e > r1) e = r1;
        if (a >= e) continue;

        float s0 = 0.f, s1 = 0.f, s2 = 0.f, s3 = 0.f;
        float q0 = 0.f, q1 = 0.f, q2 = 0.f, q3 = 0.f;

        int r = a + rsub;
        for (; r + 24 < e; r += 32) {
            float4 v0 = __ldcs(&data[(size_t)r * 32 + lane]);
            float4 v1 = __ldcs(&data[(size_t)(r + 8) * 32 + lane]);
            float4 v2 = __ldcs(&data[(size_t)(r + 16) * 32 + lane]);
            float4 v3 = __ldcs(&data[(size_t)(r + 24) * 32 + lane]);
            s0 += v0.x; q0 = fmaf(v0.x, v0.x, q0);
            s1 += v0.y; q1 = fmaf(v0.y, v0.y, q1);
            s2 += v0.z; q2 = fmaf(v0.z, v0.z, q2);
            s3 += v0.w; q3 = fmaf(v0.w, v0.w, q3);
            s0 += v1.x; q0 = fmaf(v1.x, v1.x, q0);
            s1 += v1.y; q1 = fmaf(v1.y, v1.y, q1);
            s2 += v1.z; q2 = fmaf(v1.z, v1.z, q2);
            s3 += v1.w; q3 = fmaf(v1.w, v1.w, q3);
            s0 += v2.x; q0 = fmaf(v2.x, v2.x, q0);
            s1 += v2.y; q1 = fmaf(v2.y, v2.y, q1);
            s2 += v2.z; q2 = fmaf(v2.z, v2.z, q2);
            s3 += v2.w; q3 = fmaf(v2.w, v2.w, q3);
            s0 += v3.x; q0 = fmaf(v3.x, v3.x, q0);
            s1 += v3.y; q1 = fmaf(v3.y, v3.y, q1);
            s2 += v3.z; q2 = fmaf(v3.z, v3.z, q2);
            s3 += v3.w; q3 = fmaf(v3.w, v3.w, q3);
        }
        for (; r < e; r += 8) {
            float4 v = __ldcs(&data[(size_t)r * 32 + lane]);
            s0 += v.x; q0 = fmaf(v.x, v.x, q0);
            s1 += v.y; q1 = fmaf(v.y, v.y, q1);
            s2 += v.z; q2 = fmaf(v.z, v.z, q2);
            s3 += v.w; q3 = fmaf(v.w, v.w, q3);
        }

        double* ps = &g_sum[seg * C_CH + lane * 4];
        double* pq = &g_sqs[seg * C_CH + lane * 4];
        atomicAdd(ps + 0, (double)s0);
        atomicAdd(ps + 1, (double)s1);
        atomicAdd(ps + 2, (double)s2);
        atomicAdd(ps + 3, (double)s3);
        atomicAdd(pq + 0, (double)q0);
        atomicAdd(pq + 1, (double)q1);
        atomicAdd(pq + 2, (double)q2);
        atomicAdd(pq + 3, (double)q3);
    }
}

// ---------------------------------------------------------------------------
// 2) finalize: one block per batch, 32 threads = 32 groups. Counts from bounds.
// ---------------------------------------------------------------------------
__global__ void dogn_finalize(const float* __restrict__ w,
                              const float* __restrict__ bias) {
    int b = blockIdx.x;
    if (b >= g_nseg) return;
    int g = threadIdx.x;

    int nb = g_bounds[b + 1] - g_bounds[b];
    double ic = 1.0 / (4.0 * (double)nb + (double)EPSF);

    double T1 = 0.0, T2 = 0.0;
#pragma unroll
    for (int k = 0; k < 4; k++) {
        T1 += g_sum[b * C_CH + g * 4 + k];
        T2 += g_sqs[b * C_CH + g * 4 + k];
    }
    double m   = T1 * ic;
    double var = (T2 - 2.0 * m * T1 + 4.0 * (double)nb * m * m) * ic;
    double is  = 1.0 / sqrt(var + (double)EPSF);

    float4 sc, sh;
    float wv, bv;
    wv = __ldg(&w[g * 4 + 0]); bv = __ldg(&bias[g * 4 + 0]);
    sc.x = (float)(is * wv);   sh.x = (float)(bv - m * is * wv);
    wv = __ldg(&w[g * 4 + 1]); bv = __ldg(&bias[g * 4 + 1]);
    sc.y = (float)(is * wv);   sh.y = (float)(bv - m * is * wv);
    wv = __ldg(&w[g * 4 + 2]); bv = __ldg(&bias[g * 4 + 2]);
    sc.z = (float)(is * wv);   sh.z = (float)(bv - m * is * wv);
    wv = __ldg(&w[g * 4 + 3]); bv = __ldg(&bias[g * 4 + 3]);
    sc.w = (float)(is * wv);   sh.w = (float)(bv - m * is * wv);

    g_scale[b * NGROUP + g] = sc;
    g_shift[b * NGROUP + g] = sh;
}

// ---------------------------------------------------------------------------
// 3) normalize: block owns contiguous row chunk; per overlapping segment,
//    scale/shift live in REGISTERS (lane fixed per thread), loop is a pure
//    ldcs -> FFMA -> stcs stream with no lookups.
// ---------------------------------------------------------------------------
__global__ void dogn_norm(const float4* __restrict__ data,
                          float4* __restrict__ out,
                          int n, int rows_per_block) {
    __shared__ int sb[BMAX + 1];
    __shared__ int sB;
    if (threadIdx.x == 0) sB = g_nseg;
    __syncthreads();
    int B = sB;
    for (int j = threadIdx.x; j <= B; j += blockDim.x) sb[j] = g_bounds[j];
    __syncthreads();

    const int lane = threadIdx.x & 31;
    const int rsub = threadIdx.x >> 5;
    int r0 = blockIdx.x * rows_per_block;
    int r1 = r0 + rows_per_block;
    if (r1 > n) r1 = n;
    if (r0 >= r1) return;

    for (int seg = 0; seg < B; seg++) {
        int a = sb[seg], e = sb[seg + 1];
        if (a < r0) a = r0;
        if (e > r1) e = r1;
        if (a >= e) continue;

        float4 sc = g_scale[seg * NGROUP + lane];
        float4 sh = g_shift[seg * NGROUP + lane];

        int r = a + rsub;
        for (; r + 24 < e; r += 32) {
            float4 v0 = __ldcs(&data[(size_t)r * 32 + lane]);
            float4 v1 = __ldcs(&data[(size_t)(r + 8) * 32 + lane]);
            float4 v2 = __ldcs(&data[(size_t)(r + 16) * 32 + lane]);
            float4 v3 = __ldcs(&data[(size_t)(r + 24) * 32 + lane]);
            v0.x = fmaf(v0.x, sc.x, sh.x);
            v0.y = fmaf(v0.y, sc.y, sh.y);
            v0.z = fmaf(v0.z, sc.z, sh.z);
            v0.w = fmaf(v0.w, sc.w, sh.w);
            v1.x = fmaf(v1.x, sc.x, sh.x);
            v1.y = fmaf(v1.y, sc.y, sh.y);
            v1.z = fmaf(v1.z, sc.z, sh.z);
            v1.w = fmaf(v1.w, sc.w, sh.w);
            v2.x = fmaf(v2.x, sc.x, sh.x);
            v2.y = fmaf(v2.y, sc.y, sh.y);
            v2.z = fmaf(v2.z, sc.z, sh.z);
            v2.w = fmaf(v2.w, sc.w, sh.w);
            v3.x = fmaf(v3.x, sc.x, sh.x);
            v3.y = fmaf(v3.y, sc.y, sh.y);
            v3.z = fmaf(v3.z, sc.z, sh.z);
            v3.w = fmaf(v3.w, sc.w, sh.w);
            __stcs(&out[(size_t)r * 32 + lane], v0);
            __stcs(&out[(size_t)(r + 8) * 32 + lane], v1);
            __stcs(&out[(size_t)(r + 16) * 32 + lane], v2);
            __stcs(&out[(size_t)(r + 24) * 32 + lane], v3);
        }
        for (; r < e; r += 8) {
            float4 v = __ldcs(&data[(size_t)r * 32 + lane]);
            v.x = fmaf(v.x, sc.x, sh.x);
            v.y = fmaf(v.y, sc.y, sh.y);
            v.z = fmaf(v.z, sc.z, sh.z);
            v.w = fmaf(v.w, sc.w, sh.w);
            __stcs(&out[(size_t)r * 32 + lane], v);
        }
    }
}

// ---------------------------------------------------------------------------
extern "C" void kernel_launch(void* const* d_in, const int* in_sizes, int n_in,
                              void* d_out, int out_size) {
    const float* data = (const float*)d_in[0];
    const float* w    = (const float*)d_in[1];
    const float* bias = (const float*)d_in[2];
    const int*   bid  = (const int*)d_in[3];
    const int*   bsz  = (const int*)d_in[4];

    int n = in_sizes[0] / C_CH;   // rows

    // 0) zero accumulators + segment bounds
    dogn_setup<<<17, 512>>>(bid, n, bsz);

    // 1) stats
    const int GRID = 1184;   // 8 blocks/SM on 148 SMs
    int rpb = (n + GRID - 1) / GRID;
    dogn_stats<<<GRID, 256>>>((const float4*)data, n, rpb);

    // 2) finalize
    dogn_finalize<<<BMAX, 32>>>(w, bias);

    // 3) normalize
    dogn_norm<<<GRID, 256>>>((const float4*)data, (float4*)d_out, n, rpb);
}